// round 6
// baseline (speedup 1.0000x reference)
#include <cuda_runtime.h>
#include <cuda_bf16.h>
#include <math.h>

// ---------------------------------------------------------------------------
// GMMSegHead: per-pixel LN(D=64) -> l2norm -> 95 diag-Gaussian logprobs ->
// max over P=5 -> LN over K=19.  Fully thread-local per pixel.
// One thread handles 2 adjacent pixels packed in f32x2 lanes (fma.rn.f32x2).
// ---------------------------------------------------------------------------

#define Dd    64
#define Kk    19
#define Pp    5
#define KP    95
#define NPIX  32768
#define NB    8
#define NTOT  (NB * NPIX)        // 262144 pixels
#define NPAIR (NTOT / 2)         // 131072 pixel pairs
#define HALF_D_LOG2PI 58.8120661f   // 0.5 * 64 * log(2*pi)

typedef unsigned long long u64;

// Precomputed per-component weights: {inv2, inv2, w2, w2} duplicated for f32x2.
__device__ float4 g_w4[KP * Dd];
__device__ float  g_C[KP];

// ---------------- f32x2 packed helpers (Blackwell sm_100+) -----------------
__device__ __forceinline__ u64 pk2(float lo, float hi) {
    u64 r; asm("mov.b64 %0, {%1, %2};" : "=l"(r) : "f"(lo), "f"(hi)); return r;
}
__device__ __forceinline__ void upk2(u64 v, float& lo, float& hi) {
    asm("mov.b64 {%0, %1}, %2;" : "=f"(lo), "=f"(hi) : "l"(v));
}
__device__ __forceinline__ u64 f2fma(u64 a, u64 b, u64 c) {
    u64 d; asm("fma.rn.f32x2 %0, %1, %2, %3;" : "=l"(d) : "l"(a), "l"(b), "l"(c)); return d;
}
__device__ __forceinline__ u64 f2add(u64 a, u64 b) {
    u64 d; asm("add.rn.f32x2 %0, %1, %2;" : "=l"(d) : "l"(a), "l"(b)); return d;
}
__device__ __forceinline__ u64 f2mul(u64 a, u64 b) {
    u64 d; asm("mul.rn.f32x2 %0, %1, %2;" : "=l"(d) : "l"(a), "l"(b)); return d;
}
__device__ __forceinline__ u64 dup2(float s) { return pk2(s, s); }

// ---------------------------------------------------------------------------
// Kernel 1: prep.  l2-normalize means, derive inv2 = 1/diag^2,
// w2 = -2*mu*inv2 (duplicated for packed lanes), C = -0.5*sum(mu^2*inv2)
//                                                   - sum(log diag) - 0.5*D*log(2pi)
// logp = -0.5 * sum_d x_d*(x_d*inv2_d + w2_d) + C
// ---------------------------------------------------------------------------
__global__ void prep_kernel(const float* __restrict__ means,
                            const float* __restrict__ diag) {
    int kp = blockIdx.x * blockDim.x + threadIdx.x;
    if (kp >= KP) return;
    const float* mu = means + kp * Dd;
    const float* sg = diag  + kp * Dd;

    float n2 = 0.f;
    #pragma unroll
    for (int d = 0; d < Dd; d++) n2 += mu[d] * mu[d];
    float invn = 1.f / fmaxf(sqrtf(n2), 1e-12f);

    float ct = 0.f, ls = 0.f;
    #pragma unroll
    for (int d = 0; d < Dd; d++) {
        float m  = mu[d] * invn;
        float s  = sg[d];
        float i2 = 1.f / (s * s);
        float w2 = -2.f * m * i2;
        g_w4[kp * Dd + d] = make_float4(i2, i2, w2, w2);
        ct += m * m * i2;
        ls += logf(s);
    }
    g_C[kp] = -0.5f * ct - ls - HALF_D_LOG2PI;
}

// ---------------------------------------------------------------------------
// Kernel 2: main.  Each thread owns 2 adjacent pixels (n, n+1) -> loads are
// natural float2 = packed lane pair.  Weights staged in shared (97,280 B).
// Writes raw max-over-P logprobs to out[b,k,n] (LN over K applied by kernel 3).
// ---------------------------------------------------------------------------
__global__ void __launch_bounds__(128, 2)
gmm_main(const float* __restrict__ base,
         const float* __restrict__ fw,
         const float* __restrict__ fb,
         float* __restrict__ out) {
    extern __shared__ float4 sw4[];
    for (int i = threadIdx.x; i < KP * Dd; i += 128) sw4[i] = g_w4[i];
    __syncthreads();
    const u64* sw = reinterpret_cast<const u64*>(sw4);  // 2 u64 per (kp,d)

    for (int pr = blockIdx.x * 128 + threadIdx.x; pr < NPAIR;
         pr += gridDim.x * 128) {
        int n2 = pr << 1;
        int b  = n2 >> 15;           // / NPIX
        int n  = n2 & (NPIX - 1);
        const float* bp = base + (((size_t)b * Dd) << 15) + n;

        u64 x[Dd];
        #pragma unroll
        for (int d = 0; d < Dd; d++)
            x[d] = *reinterpret_cast<const u64*>(bp + ((size_t)d << 15));

        // ---- LayerNorm over D (packed) ----
        u64 s = dup2(0.f);
        #pragma unroll
        for (int d = 0; d < Dd; d++) s = f2add(s, x[d]);
        u64 mean = f2mul(s, dup2(1.f / 64.f));
        u64 neg1 = dup2(-1.f);
        u64 vs = dup2(0.f);
        #pragma unroll
        for (int d = 0; d < Dd; d++) {
            u64 dl = f2fma(mean, neg1, x[d]);   // x - mean
            vs = f2fma(dl, dl, vs);
        }
        float v0, v1; upk2(vs, v0, v1);
        float r0 = rsqrtf(v0 * (1.f / 64.f) + 1e-5f);
        float r1 = rsqrtf(v1 * (1.f / 64.f) + 1e-5f);
        u64 rstd = pk2(r0, r1);

        // ---- affine LN + accumulate L2 norm ----
        u64 s2 = dup2(0.f);
        #pragma unroll
        for (int d = 0; d < Dd; d++) {
            u64 dl = f2fma(mean, neg1, x[d]);
            dl = f2mul(dl, rstd);
            u64 y = f2fma(dl, dup2(__ldg(fw + d)), dup2(__ldg(fb + d)));
            x[d] = y;
            s2 = f2fma(y, y, s2);
        }
        float q0, q1; upk2(s2, q0, q1);
        float i0 = 1.f / fmaxf(sqrtf(q0), 1e-12f);
        float i1 = 1.f / fmaxf(sqrtf(q1), 1e-12f);
        u64 invn = pk2(i0, i1);
        #pragma unroll
        for (int d = 0; d < Dd; d++) x[d] = f2mul(x[d], invn);

        // ---- GMM logprobs, max over P, write raw per-k values ----
        float* op = out + (((size_t)b * Kk) << 15) + n;
        int kp = 0;
        for (int k = 0; k < Kk; k++) {
            float m0 = -1e30f, m1 = -1e30f;
            for (int p = 0; p < Pp; p++, kp++) {
                const u64* wp = sw + (kp << 7);     // 128 u64 per component
                u64 a0 = dup2(0.f), a1 = dup2(0.f);
                #pragma unroll
                for (int d = 0; d < Dd; d += 2) {
                    ulonglong2 w0 = *reinterpret_cast<const ulonglong2*>(wp + 2 * d);
                    u64 t0 = f2fma(x[d], w0.x, w0.y);      // x*inv2 + w2
                    a0 = f2fma(x[d], t0, a0);              // acc += x*t
                    ulonglong2 w1 = *reinterpret_cast<const ulonglong2*>(wp + 2 * d + 2);
                    u64 t1 = f2fma(x[d + 1], w1.x, w1.y);
                    a1 = f2fma(x[d + 1], t1, a1);
                }
                u64 acc = f2add(a0, a1);
                float c = __ldg(&g_C[kp]);
                u64 lp = f2fma(acc, dup2(-0.5f), dup2(c));
                float l0, l1; upk2(lp, l0, l1);
                m0 = fmaxf(m0, l0);
                m1 = fmaxf(m1, l1);
            }
            *reinterpret_cast<u64*>(op) = pk2(m0, m1);
            op += NPIX;
        }
    }
}

// ---------------------------------------------------------------------------
// Kernel 3: in-place LayerNorm over K=19 per pixel pair.
// ---------------------------------------------------------------------------
__global__ void __launch_bounds__(256)
mask_ln(float* __restrict__ out,
        const float* __restrict__ mw,
        const float* __restrict__ mb) {
    int pr = blockIdx.x * 256 + threadIdx.x;
    if (pr >= NPAIR) return;
    int n2 = pr << 1;
    int b  = n2 >> 15;
    int n  = n2 & (NPIX - 1);
    float* op = out + (((size_t)b * Kk) << 15) + n;

    u64 v[Kk];
    #pragma unroll
    for (int k = 0; k < Kk; k++)
        v[k] = *reinterpret_cast<const u64*>(op + ((size_t)k << 15));

    u64 s = v[0];
    #pragma unroll
    for (int k = 1; k < Kk; k++) s = f2add(s, v[k]);
    u64 mean = f2mul(s, dup2(1.f / 19.f));
    u64 neg1 = dup2(-1.f);
    u64 vs = dup2(0.f);
    #pragma unroll
    for (int k = 0; k < Kk; k++) {
        u64 dl = f2fma(mean, neg1, v[k]);
        vs = f2fma(dl, dl, vs);
    }
    float v0, v1; upk2(vs, v0, v1);
    float r0 = rsqrtf(v0 * (1.f / 19.f) + 1e-5f);
    float r1 = rsqrtf(v1 * (1.f / 19.f) + 1e-5f);
    u64 rstd = pk2(r0, r1);

    #pragma unroll
    for (int k = 0; k < Kk; k++) {
        u64 dl = f2fma(mean, neg1, v[k]);
        dl = f2mul(dl, rstd);
        u64 y = f2fma(dl, dup2(__ldg(mw + k)), dup2(__ldg(mb + k)));
        *reinterpret_cast<u64*>(op + ((size_t)k << 15)) = y;
    }
}

// ---------------------------------------------------------------------------
extern "C" void kernel_launch(void* const* d_in, const int* in_sizes, int n_in,
                              void* d_out, int out_size) {
    const float* base  = (const float*)d_in[0];
    const float* means = (const float*)d_in[1];
    const float* diag  = (const float*)d_in[2];
    const float* fw    = (const float*)d_in[3];
    const float* fb    = (const float*)d_in[4];
    const float* mw    = (const float*)d_in[5];
    const float* mb    = (const float*)d_in[6];
    float* out = (float*)d_out;

    const int smem = KP * Dd * (int)sizeof(float4);   // 97,280 B
    cudaFuncSetAttribute(gmm_main, cudaFuncAttributeMaxDynamicSharedMemorySize, smem);

    prep_kernel<<<1, 128>>>(means, diag);
    gmm_main<<<296, 128, smem>>>(base, fw, fb, out);
    mask_ln<<<NPAIR / 256, 256>>>(out, mw, mb);
}

// round 12
// speedup vs baseline: 1.6865x; 1.6865x over previous
#include <cuda_runtime.h>
#include <cuda_bf16.h>
#include <math.h>

// ---------------------------------------------------------------------------
// GMMSegHead: per-pixel LN(D=64) -> l2norm -> 95 diag-Gaussian logprobs ->
// max over P=5 -> LN over K=19.  Fully thread-local per pixel.
// One thread handles 2 adjacent pixels packed in f32x2 lanes (fma.rn.f32x2).
// R7: parallel prep; mask-LN fused into main; uniform-inv2 fast path (1 FMA2
// per (kp,d) when all components share the same diagonal, verified on-chip).
// ---------------------------------------------------------------------------

#define Dd    64
#define Kk    19
#define Pp    5
#define KP    95
#define NPIX  32768
#define NB    8
#define NTOT  (NB * NPIX)        // 262144 pixels
#define NPAIR (NTOT / 2)         // 131072 pixel pairs
#define HALF_D_LOG2PI 58.8120661f   // 0.5 * 64 * log(2*pi)

typedef unsigned long long u64;

// Precomputed per-component weights: {inv2, inv2, w2, w2} duplicated for f32x2.
__device__ float4 g_w4[KP * Dd];
__device__ float  g_C[KP];

// ---------------- f32x2 packed helpers (Blackwell sm_100+) -----------------
__device__ __forceinline__ u64 pk2(float lo, float hi) {
    u64 r; asm("mov.b64 %0, {%1, %2};" : "=l"(r) : "f"(lo), "f"(hi)); return r;
}
__device__ __forceinline__ void upk2(u64 v, float& lo, float& hi) {
    asm("mov.b64 {%0, %1}, %2;" : "=f"(lo), "=f"(hi) : "l"(v));
}
__device__ __forceinline__ u64 f2fma(u64 a, u64 b, u64 c) {
    u64 d; asm("fma.rn.f32x2 %0, %1, %2, %3;" : "=l"(d) : "l"(a), "l"(b), "l"(c)); return d;
}
__device__ __forceinline__ u64 f2add(u64 a, u64 b) {
    u64 d; asm("add.rn.f32x2 %0, %1, %2;" : "=l"(d) : "l"(a), "l"(b)); return d;
}
__device__ __forceinline__ u64 f2mul(u64 a, u64 b) {
    u64 d; asm("mul.rn.f32x2 %0, %1, %2;" : "=l"(d) : "l"(a), "l"(b)); return d;
}
__device__ __forceinline__ u64 dup2(float s) { return pk2(s, s); }

// ---------------------------------------------------------------------------
// Kernel 1: prep (parallel: one warp per component).
// l2-normalize means; inv2 = 1/diag^2; w2 = -2*mu*inv2;
// C = -0.5*sum(mu^2*inv2) - sum(log diag) - 0.5*D*log(2pi)
// logp = -0.5 * (sum_d x_d^2*inv2_d + sum_d w2_d*x_d) + C
// ---------------------------------------------------------------------------
__global__ void __launch_bounds__(128)
prep_kernel(const float* __restrict__ means,
            const float* __restrict__ diag) {
    int w    = (blockIdx.x * 128 + threadIdx.x) >> 5;
    int lane = threadIdx.x & 31;
    if (w >= KP) return;
    const float* mu = means + w * Dd;
    const float* sg = diag  + w * Dd;

    float m0 = mu[lane], m1 = mu[lane + 32];
    float n2 = m0 * m0 + m1 * m1;
    #pragma unroll
    for (int o = 16; o > 0; o >>= 1) n2 += __shfl_xor_sync(0xffffffffu, n2, o);
    float invn = 1.f / fmaxf(sqrtf(n2), 1e-12f);

    float ct = 0.f, ls = 0.f;
    #pragma unroll
    for (int h = 0; h < 2; h++) {
        int d = lane + h * 32;
        float m  = mu[d] * invn;
        float s  = sg[d];
        float i2 = 1.f / (s * s);
        float w2 = -2.f * m * i2;
        g_w4[w * Dd + d] = make_float4(i2, i2, w2, w2);
        ct += m * m * i2;
        ls += logf(s);
    }
    #pragma unroll
    for (int o = 16; o > 0; o >>= 1) {
        ct += __shfl_xor_sync(0xffffffffu, ct, o);
        ls += __shfl_xor_sync(0xffffffffu, ls, o);
    }
    if (lane == 0) g_C[w] = -0.5f * ct - ls - HALF_D_LOG2PI;
}

// ---------------------------------------------------------------------------
// Kernel 2: main (fused).  Each thread owns 2 adjacent pixels.  Weights in
// shared (97,280 B).  After staging, block verifies whether inv2 is identical
// across all KP components; if so, uses the 1-FMA2/(kp,d) dot-product path.
// Epilogue LN over K=19 done in-register; single write of out[b,k,n].
// ---------------------------------------------------------------------------
__global__ void __launch_bounds__(128, 2)
gmm_main(const float* __restrict__ base,
         const float* __restrict__ fw,
         const float* __restrict__ fb,
         const float* __restrict__ mw,
         const float* __restrict__ mb,
         float* __restrict__ out) {
    extern __shared__ float4 sw4[];
    for (int i = threadIdx.x; i < KP * Dd; i += 128) sw4[i] = g_w4[i];
    __syncthreads();
    const u64* sw = reinterpret_cast<const u64*>(sw4);  // [2*(kp*64+d)] = inv2dup, +1 = w2dup

    // Uniform-diagonal check: inv2[kp][d] == inv2[0][d] for all kp?
    int ok = 1;
    for (int i = threadIdx.x; i < KP * Dd; i += 128)
        ok &= (sw4[i].x == sw4[i & (Dd - 1)].x);
    int same = __syncthreads_and(ok);

    for (int pr = blockIdx.x * 128 + threadIdx.x; pr < NPAIR;
         pr += gridDim.x * 128) {
        int n2i = pr << 1;
        int b   = n2i >> 15;           // / NPIX
        int n   = n2i & (NPIX - 1);
        const float* bp = base + (((size_t)b * Dd) << 15) + n;

        u64 x[Dd];
        #pragma unroll
        for (int d = 0; d < Dd; d++)
            x[d] = *reinterpret_cast<const u64*>(bp + ((size_t)d << 15));

        // ---- LayerNorm over D (packed) ----
        u64 s = dup2(0.f);
        #pragma unroll
        for (int d = 0; d < Dd; d++) s = f2add(s, x[d]);
        u64 mean = f2mul(s, dup2(1.f / 64.f));
        u64 neg1 = dup2(-1.f);
        u64 vs = dup2(0.f);
        #pragma unroll
        for (int d = 0; d < Dd; d++) {
            u64 dl = f2fma(mean, neg1, x[d]);   // x - mean
            vs = f2fma(dl, dl, vs);
        }
        float v0, v1; upk2(vs, v0, v1);
        float r0 = rsqrtf(v0 * (1.f / 64.f) + 1e-5f);
        float r1 = rsqrtf(v1 * (1.f / 64.f) + 1e-5f);
        u64 rstd = pk2(r0, r1);

        // ---- affine LN + accumulate L2 norm ----
        u64 s2 = dup2(0.f);
        #pragma unroll
        for (int d = 0; d < Dd; d++) {
            u64 dl = f2fma(mean, neg1, x[d]);
            dl = f2mul(dl, rstd);
            u64 y = f2fma(dl, dup2(__ldg(fw + d)), dup2(__ldg(fb + d)));
            x[d] = y;
            s2 = f2fma(y, y, s2);
        }
        float q0f, q1f; upk2(s2, q0f, q1f);
        float i0 = 1.f / fmaxf(sqrtf(q0f), 1e-12f);
        float i1 = 1.f / fmaxf(sqrtf(q1f), 1e-12f);
        u64 invn = pk2(i0, i1);
        #pragma unroll
        for (int d = 0; d < Dd; d++) x[d] = f2mul(x[d], invn);

        // ---- GMM logprobs, max over P, LN over K, single write ----
        float mk0[Kk], mk1[Kk];

        if (same) {
            // q0 = sum_d x_d^2 * inv2_d  (inv2 row of component 0)
            u64 qa = dup2(0.f), qb = dup2(0.f);
            #pragma unroll
            for (int d = 0; d < Dd; d += 2) {
                qa = f2fma(f2mul(x[d],     x[d]),     sw[2 * d],       qa);
                qb = f2fma(f2mul(x[d + 1], x[d + 1]), sw[2 * (d + 1)], qb);
            }
            u64 q0 = f2add(qa, qb);

            int kp = 0;
            for (int k = 0; k < Kk; k++) {
                float m0 = -1e30f, m1 = -1e30f;
                for (int p = 0; p < Pp; p++, kp++) {
                    const u64* wp = sw + (kp << 7);
                    u64 a0 = dup2(0.f), a1 = dup2(0.f);
                    #pragma unroll
                    for (int d = 0; d < Dd; d += 2) {
                        a0 = f2fma(x[d],     wp[2 * d + 1],     a0);
                        a1 = f2fma(x[d + 1], wp[2 * d + 3],     a1);
                    }
                    u64 quad = f2add(f2add(a0, a1), q0);
                    u64 lp = f2fma(quad, dup2(-0.5f), dup2(__ldg(&g_C[kp])));
                    float l0, l1; upk2(lp, l0, l1);
                    m0 = fmaxf(m0, l0);
                    m1 = fmaxf(m1, l1);
                }
                mk0[k] = m0; mk1[k] = m1;
            }
        } else {
            int kp = 0;
            for (int k = 0; k < Kk; k++) {
                float m0 = -1e30f, m1 = -1e30f;
                for (int p = 0; p < Pp; p++, kp++) {
                    const u64* wp = sw + (kp << 7);
                    u64 a0 = dup2(0.f), a1 = dup2(0.f);
                    #pragma unroll
                    for (int d = 0; d < Dd; d += 2) {
                        ulonglong2 w0 = *reinterpret_cast<const ulonglong2*>(wp + 2 * d);
                        u64 t0 = f2fma(x[d], w0.x, w0.y);
                        a0 = f2fma(x[d], t0, a0);
                        ulonglong2 w1 = *reinterpret_cast<const ulonglong2*>(wp + 2 * d + 2);
                        u64 t1 = f2fma(x[d + 1], w1.x, w1.y);
                        a1 = f2fma(x[d + 1], t1, a1);
                    }
                    u64 acc = f2add(a0, a1);
                    u64 lp = f2fma(acc, dup2(-0.5f), dup2(__ldg(&g_C[kp])));
                    float l0, l1; upk2(lp, l0, l1);
                    m0 = fmaxf(m0, l0);
                    m1 = fmaxf(m1, l1);
                }
                mk0[k] = m0; mk1[k] = m1;
            }
        }

        // ---- in-register LayerNorm over K=19 ----
        {
            u64 v[Kk];
            #pragma unroll
            for (int k = 0; k < Kk; k++) v[k] = pk2(mk0[k], mk1[k]);
            u64 sk = v[0];
            #pragma unroll
            for (int k = 1; k < Kk; k++) sk = f2add(sk, v[k]);
            u64 meank = f2mul(sk, dup2(1.f / 19.f));
            u64 vsk = dup2(0.f);
            #pragma unroll
            for (int k = 0; k < Kk; k++) {
                u64 dl = f2fma(meank, neg1, v[k]);
                vsk = f2fma(dl, dl, vsk);
            }
            float w0, w1; upk2(vsk, w0, w1);
            float rr0 = rsqrtf(w0 * (1.f / 19.f) + 1e-5f);
            float rr1 = rsqrtf(w1 * (1.f / 19.f) + 1e-5f);
            u64 rstdk = pk2(rr0, rr1);

            float* op = out + (((size_t)b * Kk) << 15) + n;
            #pragma unroll
            for (int k = 0; k < Kk; k++) {
                u64 dl = f2fma(meank, neg1, v[k]);
                dl = f2mul(dl, rstdk);
                u64 y = f2fma(dl, dup2(__ldg(mw + k)), dup2(__ldg(mb + k)));
                *reinterpret_cast<u64*>(op + ((size_t)k << 15)) = y;
            }
        }
    }
}

// ---------------------------------------------------------------------------
extern "C" void kernel_launch(void* const* d_in, const int* in_sizes, int n_in,
                              void* d_out, int out_size) {
    const float* base  = (const float*)d_in[0];
    const float* means = (const float*)d_in[1];
    const float* diag  = (const float*)d_in[2];
    const float* fw    = (const float*)d_in[3];
    const float* fb    = (const float*)d_in[4];
    const float* mw    = (const float*)d_in[5];
    const float* mb    = (const float*)d_in[6];
    float* out = (float*)d_out;

    const int smem = KP * Dd * (int)sizeof(float4);   // 97,280 B
    cudaFuncSetAttribute(gmm_main, cudaFuncAttributeMaxDynamicSharedMemorySize, smem);

    prep_kernel<<<24, 128>>>(means, diag);            // 96 warps, 1 per component
    gmm_main<<<296, 128, smem>>>(base, fw, fb, mw, mb, out);
}

// round 13
// speedup vs baseline: 1.8425x; 1.0925x over previous
#include <cuda_runtime.h>
#include <cuda_bf16.h>
#include <math.h>

// ---------------------------------------------------------------------------
// GMMSegHead R13: per-pixel LN(64) -> l2norm -> 95 logprobs -> max P -> LN(19).
// Pixel-pair per thread in f32x2.  Fast kernel (uniform diagonal, verified by
// prep) uses compact w2-only weights loaded as LDS.128; slow kernel keeps the
// general path.  Exactly one of the two does work per launch.
// ---------------------------------------------------------------------------

#define Dd    64
#define Kk    19
#define Pp    5
#define KP    95
#define NPIX  32768
#define NB    8
#define NTOT  (NB * NPIX)
#define NPAIR (NTOT / 2)
#define HALF_D_LOG2PI 58.8120661f

typedef unsigned long long u64;

__device__ float4 g_w4[KP * Dd];      // {inv2,inv2,w2,w2} for slow path
__device__ u64    g_w2dup[KP * Dd];   // {w2,w2} compact for fast path
__device__ u64    g_inv2dup[Dd];      // {inv2,inv2} row of component 0
__device__ float  g_C[KP];
__device__ int    g_sameArr[KP];      // per-component: inv2 row == row 0?

// ---------------- f32x2 packed helpers -----------------
__device__ __forceinline__ u64 pk2(float lo, float hi) {
    u64 r; asm("mov.b64 %0, {%1, %2};" : "=l"(r) : "f"(lo), "f"(hi)); return r;
}
__device__ __forceinline__ void upk2(u64 v, float& lo, float& hi) {
    asm("mov.b64 {%0, %1}, %2;" : "=f"(lo), "=f"(hi) : "l"(v));
}
__device__ __forceinline__ u64 f2fma(u64 a, u64 b, u64 c) {
    u64 d; asm("fma.rn.f32x2 %0, %1, %2, %3;" : "=l"(d) : "l"(a), "l"(b), "l"(c)); return d;
}
__device__ __forceinline__ u64 f2add(u64 a, u64 b) {
    u64 d; asm("add.rn.f32x2 %0, %1, %2;" : "=l"(d) : "l"(a), "l"(b)); return d;
}
__device__ __forceinline__ u64 f2mul(u64 a, u64 b) {
    u64 d; asm("mul.rn.f32x2 %0, %1, %2;" : "=l"(d) : "l"(a), "l"(b)); return d;
}
__device__ __forceinline__ u64 dup2(float s) { return pk2(s, s); }

// ---------------------------------------------------------------------------
// prep: one warp per component.
// ---------------------------------------------------------------------------
__global__ void __launch_bounds__(128)
prep_kernel(const float* __restrict__ means,
            const float* __restrict__ diag) {
    int w    = (blockIdx.x * 128 + threadIdx.x) >> 5;
    int lane = threadIdx.x & 31;
    if (w >= KP) return;
    const float* mu = means + w * Dd;
    const float* sg = diag  + w * Dd;

    float m0 = mu[lane], m1 = mu[lane + 32];
    float n2 = m0 * m0 + m1 * m1;
    #pragma unroll
    for (int o = 16; o > 0; o >>= 1) n2 += __shfl_xor_sync(0xffffffffu, n2, o);
    float invn = 1.f / fmaxf(sqrtf(n2), 1e-12f);

    float ct = 0.f, ls = 0.f;
    int ok = 1;
    #pragma unroll
    for (int h = 0; h < 2; h++) {
        int d = lane + h * 32;
        float m  = mu[d] * invn;
        float s  = sg[d];
        float i2 = 1.f / (s * s);
        float w2 = -2.f * m * i2;
        g_w4[w * Dd + d]    = make_float4(i2, i2, w2, w2);
        g_w2dup[w * Dd + d] = pk2(w2, w2);
        if (w == 0) g_inv2dup[d] = pk2(i2, i2);
        // uniformity vs component-0 diagonal (read directly from input row 0)
        float s0  = diag[d];
        float i2r = 1.f / (s0 * s0);
        ok &= (i2 == i2r);
        ct += m * m * i2;
        ls += logf(s);
    }
    ok = __all_sync(0xffffffffu, ok);
    #pragma unroll
    for (int o = 16; o > 0; o >>= 1) {
        ct += __shfl_xor_sync(0xffffffffu, ct, o);
        ls += __shfl_xor_sync(0xffffffffu, ls, o);
    }
    if (lane == 0) {
        g_C[w] = -0.5f * ct - ls - HALF_D_LOG2PI;
        g_sameArr[w] = ok;
    }
}

// ---------------------------------------------------------------------------
// Shared front half: load pair, LN over D, l2-normalize.  (macro-free inline)
// ---------------------------------------------------------------------------
__device__ __forceinline__ void ln_l2(const float* __restrict__ bp,
                                      const float* __restrict__ fw,
                                      const float* __restrict__ fb,
                                      u64* x) {
    #pragma unroll
    for (int d = 0; d < Dd; d++)
        x[d] = *reinterpret_cast<const u64*>(bp + ((size_t)d << 15));

    u64 s = dup2(0.f);
    #pragma unroll
    for (int d = 0; d < Dd; d++) s = f2add(s, x[d]);
    u64 mean = f2mul(s, dup2(1.f / 64.f));
    u64 neg1 = dup2(-1.f);
    u64 vs = dup2(0.f);
    #pragma unroll
    for (int d = 0; d < Dd; d++) {
        u64 dl = f2fma(mean, neg1, x[d]);
        vs = f2fma(dl, dl, vs);
    }
    float v0, v1; upk2(vs, v0, v1);
    u64 rstd = pk2(rsqrtf(v0 * (1.f / 64.f) + 1e-5f),
                   rsqrtf(v1 * (1.f / 64.f) + 1e-5f));

    u64 s2 = dup2(0.f);
    #pragma unroll
    for (int d = 0; d < Dd; d++) {
        u64 dl = f2fma(mean, neg1, x[d]);
        dl = f2mul(dl, rstd);
        u64 y = f2fma(dl, dup2(__ldg(fw + d)), dup2(__ldg(fb + d)));
        x[d] = y;
        s2 = f2fma(y, y, s2);
    }
    float q0f, q1f; upk2(s2, q0f, q1f);
    u64 invn = pk2(1.f / fmaxf(sqrtf(q0f), 1e-12f),
                   1.f / fmaxf(sqrtf(q1f), 1e-12f));
    #pragma unroll
    for (int d = 0; d < Dd; d++) x[d] = f2mul(x[d], invn);
}

// Shared epilogue: in-register LN over K and store.
__device__ __forceinline__ void mask_ln_store(const float* mk0, const float* mk1,
                                              const float* __restrict__ mw,
                                              const float* __restrict__ mb,
                                              float* __restrict__ op) {
    u64 v[Kk];
    #pragma unroll
    for (int k = 0; k < Kk; k++) v[k] = pk2(mk0[k], mk1[k]);
    u64 sk = v[0];
    #pragma unroll
    for (int k = 1; k < Kk; k++) sk = f2add(sk, v[k]);
    u64 meank = f2mul(sk, dup2(1.f / 19.f));
    u64 neg1  = dup2(-1.f);
    u64 vsk = dup2(0.f);
    #pragma unroll
    for (int k = 0; k < Kk; k++) {
        u64 dl = f2fma(meank, neg1, v[k]);
        vsk = f2fma(dl, dl, vsk);
    }
    float w0, w1; upk2(vsk, w0, w1);
    u64 rstdk = pk2(rsqrtf(w0 * (1.f / 19.f) + 1e-5f),
                    rsqrtf(w1 * (1.f / 19.f) + 1e-5f));
    #pragma unroll
    for (int k = 0; k < Kk; k++) {
        u64 dl = f2fma(meank, neg1, v[k]);
        dl = f2mul(dl, rstdk);
        u64 y = f2fma(dl, dup2(__ldg(mw + k)), dup2(__ldg(mb + k)));
        *reinterpret_cast<u64*>(op + ((size_t)k << 15)) = y;
    }
}

// ---------------------------------------------------------------------------
// FAST kernel: uniform diagonal across components.  Compact w2 weights,
// LDS.128 loads.  smem = (64 + 6080) * 8 = 49,152 B.
// ---------------------------------------------------------------------------
__global__ void __launch_bounds__(128, 2)
gmm_fast(const float* __restrict__ base,
         const float* __restrict__ fw,
         const float* __restrict__ fb,
         const float* __restrict__ mw,
         const float* __restrict__ mb,
         float* __restrict__ out) {
    extern __shared__ u64 sm[];            // [0,64): inv2dup row, [64,...): w2dup

    int ok = 1;
    for (int w = threadIdx.x; w < KP; w += 128) ok &= g_sameArr[w];
    if (!__syncthreads_and(ok)) return;    // not our case

    for (int i = threadIdx.x; i < Dd; i += 128) sm[i] = g_inv2dup[i];
    for (int i = threadIdx.x; i < KP * Dd; i += 128) sm[Dd + i] = g_w2dup[i];
    __syncthreads();

    const ulonglong2* iv2 = reinterpret_cast<const ulonglong2*>(sm);

    for (int pr = blockIdx.x * 128 + threadIdx.x; pr < NPAIR;
         pr += gridDim.x * 128) {
        int n2i = pr << 1;
        int b   = n2i >> 15;
        int n   = n2i & (NPIX - 1);

        u64 x[Dd];
        ln_l2(base + (((size_t)b * Dd) << 15) + n, fw, fb, x);

        // q0 = sum x^2 * inv2  (16 LDS.128 + 32 mul + 32 fma)
        u64 qa = dup2(0.f), qb = dup2(0.f);
        #pragma unroll
        for (int d = 0; d < Dd; d += 2) {
            ulonglong2 w = iv2[d >> 1];
            qa = f2fma(f2mul(x[d],     x[d]),     w.x, qa);
            qb = f2fma(f2mul(x[d + 1], x[d + 1]), w.y, qb);
        }
        u64 q0 = f2add(qa, qb);

        float mk0[Kk], mk1[Kk];
        int kp = 0;
        for (int k = 0; k < Kk; k++) {
            float m0 = -1e30f, m1 = -1e30f;
            for (int p = 0; p < Pp; p++, kp++) {
                const ulonglong2* wp =
                    reinterpret_cast<const ulonglong2*>(sm + Dd + kp * Dd);
                u64 a0 = dup2(0.f), a1 = dup2(0.f);
                #pragma unroll
                for (int d = 0; d < Dd; d += 2) {
                    ulonglong2 w = wp[d >> 1];          // 1 LDS.128 per 2 d
                    a0 = f2fma(x[d],     w.x, a0);
                    a1 = f2fma(x[d + 1], w.y, a1);
                }
                u64 quad = f2add(f2add(a0, a1), q0);
                u64 lp = f2fma(quad, dup2(-0.5f), dup2(__ldg(&g_C[kp])));
                float l0, l1; upk2(lp, l0, l1);
                m0 = fmaxf(m0, l0);
                m1 = fmaxf(m1, l1);
            }
            mk0[k] = m0; mk1[k] = m1;
        }
        mask_ln_store(mk0, mk1, mw, mb, out + (((size_t)b * Kk) << 15) + n);
    }
}

// ---------------------------------------------------------------------------
// SLOW kernel: general per-component diagonals.  smem = 97,280 B.
// ---------------------------------------------------------------------------
__global__ void __launch_bounds__(128, 2)
gmm_slow(const float* __restrict__ base,
         const float* __restrict__ fw,
         const float* __restrict__ fb,
         const float* __restrict__ mw,
         const float* __restrict__ mb,
         float* __restrict__ out) {
    extern __shared__ float4 sw4[];

    int ok = 1;
    for (int w = threadIdx.x; w < KP; w += 128) ok &= g_sameArr[w];
    if (__syncthreads_and(ok)) return;     // fast kernel handles it

    for (int i = threadIdx.x; i < KP * Dd; i += 128) sw4[i] = g_w4[i];
    __syncthreads();
    const u64* sw = reinterpret_cast<const u64*>(sw4);

    for (int pr = blockIdx.x * 128 + threadIdx.x; pr < NPAIR;
         pr += gridDim.x * 128) {
        int n2i = pr << 1;
        int b   = n2i >> 15;
        int n   = n2i & (NPIX - 1);

        u64 x[Dd];
        ln_l2(base + (((size_t)b * Dd) << 15) + n, fw, fb, x);

        float mk0[Kk], mk1[Kk];
        int kp = 0;
        for (int k = 0; k < Kk; k++) {
            float m0 = -1e30f, m1 = -1e30f;
            for (int p = 0; p < Pp; p++, kp++) {
                const u64* wp = sw + (kp << 7);
                u64 a0 = dup2(0.f), a1 = dup2(0.f);
                #pragma unroll
                for (int d = 0; d < Dd; d += 2) {
                    ulonglong2 w0 = *reinterpret_cast<const ulonglong2*>(wp + 2 * d);
                    u64 t0 = f2fma(x[d], w0.x, w0.y);
                    a0 = f2fma(x[d], t0, a0);
                    ulonglong2 w1 = *reinterpret_cast<const ulonglong2*>(wp + 2 * d + 2);
                    u64 t1 = f2fma(x[d + 1], w1.x, w1.y);
                    a1 = f2fma(x[d + 1], t1, a1);
                }
                u64 acc = f2add(a0, a1);
                u64 lp = f2fma(acc, dup2(-0.5f), dup2(__ldg(&g_C[kp])));
                float l0, l1; upk2(lp, l0, l1);
                m0 = fmaxf(m0, l0);
                m1 = fmaxf(m1, l1);
            }
            mk0[k] = m0; mk1[k] = m1;
        }
        mask_ln_store(mk0, mk1, mw, mb, out + (((size_t)b * Kk) << 15) + n);
    }
}

// ---------------------------------------------------------------------------
extern "C" void kernel_launch(void* const* d_in, const int* in_sizes, int n_in,
                              void* d_out, int out_size) {
    const float* base  = (const float*)d_in[0];
    const float* means = (const float*)d_in[1];
    const float* diag  = (const float*)d_in[2];
    const float* fw    = (const float*)d_in[3];
    const float* fb    = (const float*)d_in[4];
    const float* mw    = (const float*)d_in[5];
    const float* mb    = (const float*)d_in[6];
    float* out = (float*)d_out;

    const int smem_fast = (Dd + KP * Dd) * (int)sizeof(u64);   // 49,152 B
    const int smem_slow = KP * Dd * (int)sizeof(float4);       // 97,280 B
    cudaFuncSetAttribute(gmm_fast, cudaFuncAttributeMaxDynamicSharedMemorySize, smem_fast);
    cudaFuncSetAttribute(gmm_slow, cudaFuncAttributeMaxDynamicSharedMemorySize, smem_slow);

    prep_kernel<<<24, 128>>>(means, diag);
    gmm_fast<<<296, 128, smem_fast>>>(base, fw, fb, mw, mb, out);
    gmm_slow<<<296, 128, smem_slow>>>(base, fw, fb, mw, mb, out);
}